// round 4
// baseline (speedup 1.0000x reference)
#include <cuda_runtime.h>

#define NBAS   2048
#define CH     8
// 4015 = 501 full chunks of 8 + 7-step tail
#define NFULL  501

__device__ __forceinline__ float sqrt_ap(float x){ float y; asm("sqrt.approx.f32 %0, %1;" : "=f"(y) : "f"(x)); return y; }
__device__ __forceinline__ float rsqrt_ap(float x){ float y; asm("rsqrt.approx.f32 %0, %1;" : "=f"(y) : "f"(x)); return y; }

// Named-barrier producer/consumer handshake (2 warps, 64 threads).
// FULL(k) = 1 + (k&1), FREE(k) = 3 + (k&1).
__device__ __forceinline__ void bar_sync_id(int id){ asm volatile("bar.sync %0, 64;" :: "r"(id)); }
__device__ __forceinline__ void bar_arrive_id(int id){ asm volatile("bar.arrive %0, 64;" :: "r"(id)); }

// ---------------- production (s store) ----------------
// tanh(x) ~ x for x <= 0.01; 1/(1+d) ~ 1-d+d^2, d <= 0.01;
// (1+y)^(-1/4), y <= 0.039 -> 4-term Taylor. s2 clip provably inactive.
struct PSt { float s, inv_x1, c49; };

__device__ __forceinline__ float prod_step(PSt& st, float2 pe){
  float diff = pe.x - pe.y;
  float pn = fmaxf(diff, 0.f);
  float en = fmaxf(-diff, 0.f);
  float xp = pn * st.inv_x1;
  float xe = en * st.inv_x1;
  float u  = st.s * st.inv_x1;
  float dp = u * xp;
  float ip = fmaf(dp, dp - 1.f, 1.f);
  float ps = pn * fmaf(-u, u, 1.f) * ip;
  float de = (1.f - u) * xe;
  float ie = fmaf(de, de - 1.f, 1.f);
  float es = st.s * (2.f - u) * xe * ie;
  float s2 = (st.s - es) + ps;
  float m  = s2 * st.c49;
  float m2 = m * m;
  float y  = m2 * m2;
  float p  = fmaf(y, fmaf(y, -15.f/128.f, 5.f/32.f), -0.25f);
  float w  = fmaf(y, p, 1.f);
  float snew = s2 * w;
  float pr = (s2 - snew) + (pn - ps);
  st.s = snew;
  return pr;
}

// ---------------- conv + routing (r store) ----------------
struct RSt {
  float r, c35, ix3_4;
  float u10,u11,u12, u20,u21,u22,u23,u24,u25;
  float h1,h2,h3,h4,h5;
};

template<bool STORE>
__device__ __forceinline__ void cons_step(RSt& st, float pr, float* op){
  float q9 = st.u10*pr + st.u11*st.h1 + st.u12*st.h2;
  float q1 = st.u20*pr + st.u21*st.h1 + st.u22*st.h2
           + st.u23*st.h3 + st.u24*st.h4 + st.u25*st.h5;
  st.h5 = st.h4; st.h4 = st.h3; st.h3 = st.h2; st.h2 = st.h1; st.h1 = pr;
  float r   = st.r;
  float gex = st.c35 * (r * r * r) * sqrt_ap(r);
  float rr  = fmaxf((r + q9) + gex, 0.f);
  float t2  = rr * rr;
  float a   = fmaf(t2 * t2, st.ix3_4, 1.f);
  float w   = rsqrt_ap(sqrt_ap(a));
  float rn  = rr * w;
  st.r = rn;
  if (STORE){
    *op = (rr - rn) + fmaxf(q1 + gex, 0.f);
  }
}

__device__ __forceinline__ void rst_init(RSt& st, float x2, float x3, float x4){
  float ix3 = 1.f / x3;
  float i2  = ix3 * ix3;
  st.c35   = x2 * (ix3 * ix3 * ix3) * sqrtf(ix3);
  st.ix3_4 = i2 * i2;
  st.r = 0.5f * x3;
  float ix4 = 1.f / x4;
  float sh1[4], sh2[7];
  #pragma unroll
  for (int t = 0; t < 4; t++){
    float a = fminf((float)t * ix4, 1.f);
    sh1[t] = a * a * sqrtf(a);
  }
  #pragma unroll
  for (int t = 0; t < 7; t++){
    float rr = (float)t * ix4; float v;
    if ((float)t <= x4){ v = 0.5f * rr * rr * sqrtf(rr); }
    else { float mm = fmaxf(2.f - rr, 0.f); v = 1.f - 0.5f * mm * mm * sqrtf(mm); }
    sh2[t] = v;
  }
  st.u10 = sh1[1]-sh1[0]; st.u11 = sh1[2]-sh1[1]; st.u12 = sh1[3]-sh1[2];
  st.u20 = sh2[1]-sh2[0]; st.u21 = sh2[2]-sh2[1]; st.u22 = sh2[3]-sh2[2];
  st.u23 = sh2[4]-sh2[3]; st.u24 = sh2[5]-sh2[4]; st.u25 = sh2[6]-sh2[5];
  st.h1=0.f; st.h2=0.f; st.h3=0.f; st.h4=0.f; st.h5=0.f;
}

__shared__ float prbuf[2][CH][64];

__global__ void __launch_bounds__(64)
gr4j_ws2(const float2* __restrict__ pe, const float4* __restrict__ prm,
         float* __restrict__ out){
  int lane = threadIdx.x & 31;
  int wid  = threadIdx.x >> 5;
  int bA   = blockIdx.x * 64 + lane;
  int bB   = bA + 32;
  float4 pmA = prm[bA];
  float4 pmB = prm[bB];

  if (wid == 0){
    // ============ PRODUCER warp: production store, 2 basins ============
    PSt sA, sB;
    float x1A = fmaf(pmA.x, 1100.f, 100.f);
    float x1B = fmaf(pmB.x, 1100.f, 100.f);
    sA.inv_x1 = 1.f / x1A;  sA.c49 = (4.f/9.f) * sA.inv_x1;  sA.s = 0.5f * x1A;
    sB.inv_x1 = 1.f / x1B;  sB.c49 = (4.f/9.f) * sB.inv_x1;  sB.s = 0.5f * x1B;

    float2 curA[CH], curB[CH], nxtA[CH], nxtB[CH];
    #pragma unroll
    for (int j = 0; j < CH; j++){ curA[j] = pe[j*NBAS + bA]; curB[j] = pe[j*NBAS + bB]; }

    for (int k = 0; k < NFULL; k++){
      int tb = (k + 1) * CH;
      #pragma unroll
      for (int j = 0; j < CH; j++){
        int tt = tb + j; tt = tt < 4015 ? tt : 4014;
        nxtA[j] = pe[tt*NBAS + bA];
        nxtB[j] = pe[tt*NBAS + bB];
      }
      if (k >= 2) bar_sync_id(3 + (k & 1));
      int buf = k & 1;
      #pragma unroll
      for (int j = 0; j < CH; j++){
        prbuf[buf][j][lane]      = prod_step(sA, curA[j]);
        prbuf[buf][j][lane + 32] = prod_step(sB, curB[j]);
      }
      bar_arrive_id(1 + (k & 1));
      #pragma unroll
      for (int j = 0; j < CH; j++){ curA[j] = nxtA[j]; curB[j] = nxtB[j]; }
    }
    // tail chunk k=501 (7 steps), buf 1
    bar_sync_id(3 + 1);
    #pragma unroll
    for (int j = 0; j < 7; j++){
      prbuf[1][j][lane]      = prod_step(sA, curA[j]);
      prbuf[1][j][lane + 32] = prod_step(sB, curB[j]);
    }
    bar_arrive_id(1 + 1);
  } else {
    // ============ CONSUMER warp: conv + routing, 2 basins ============
    RSt rA, rB;
    rst_init(rA, fmaf(pmA.y, 8.f, -5.f), fmaf(pmA.z, 280.f, 20.f), fmaf(pmA.w, 1.8f, 1.1f));
    rst_init(rB, fmaf(pmB.y, 8.f, -5.f), fmaf(pmB.z, 280.f, 20.f), fmaf(pmB.w, 1.8f, 1.1f));

    float pA[CH], pB[CH];

    // chunks 0..44: t = 0..359, no stores
    for (int k = 0; k < 45; k++){
      bar_sync_id(1 + (k & 1));
      int buf = k & 1;
      #pragma unroll
      for (int j = 0; j < CH; j++){ pA[j] = prbuf[buf][j][lane]; pB[j] = prbuf[buf][j][lane+32]; }
      bar_arrive_id(3 + (k & 1));
      #pragma unroll
      for (int j = 0; j < CH; j++){ cons_step<false>(rA, pA[j], nullptr); cons_step<false>(rB, pB[j], nullptr); }
    }

    // chunk 45: t = 360..367; reset history before t=365 (j=5); store from t=365
    {
      bar_sync_id(1 + 1);
      #pragma unroll
      for (int j = 0; j < CH; j++){ pA[j] = prbuf[1][j][lane]; pB[j] = prbuf[1][j][lane+32]; }
      bar_arrive_id(3 + 1);
      #pragma unroll
      for (int j = 0; j < 5; j++){ cons_step<false>(rA, pA[j], nullptr); cons_step<false>(rB, pB[j], nullptr); }
      rA.h1=0.f; rA.h2=0.f; rA.h3=0.f; rA.h4=0.f; rA.h5=0.f;
      rB.h1=0.f; rB.h2=0.f; rB.h3=0.f; rB.h4=0.f; rB.h5=0.f;
      #pragma unroll
      for (int j = 5; j < CH; j++){
        cons_step<true>(rA, pA[j], out + (j-5)*NBAS + bA);
        cons_step<true>(rB, pB[j], out + (j-5)*NBAS + bB);
      }
    }

    // chunks 46..500: all store (ti base = 8k - 365)
    float* opA = out + 3 * NBAS + bA;
    float* opB = out + 3 * NBAS + bB;
    for (int k = 46; k < NFULL; k++){
      bar_sync_id(1 + (k & 1));
      int buf = k & 1;
      #pragma unroll
      for (int j = 0; j < CH; j++){ pA[j] = prbuf[buf][j][lane]; pB[j] = prbuf[buf][j][lane+32]; }
      bar_arrive_id(3 + (k & 1));
      #pragma unroll
      for (int j = 0; j < CH; j++){
        cons_step<true>(rA, pA[j], opA + j*NBAS);
        cons_step<true>(rB, pB[j], opB + j*NBAS);
      }
      opA += CH * NBAS;  opB += CH * NBAS;
    }

    // tail chunk k=501: 7 steps, ti 3643..3649, buf 1
    bar_sync_id(1 + 1);
    #pragma unroll
    for (int j = 0; j < 7; j++){ pA[j] = prbuf[1][j][lane]; pB[j] = prbuf[1][j][lane+32]; }
    #pragma unroll
    for (int j = 0; j < 7; j++){
      cons_step<true>(rA, pA[j], opA + j*NBAS);
      cons_step<true>(rB, pB[j], opB + j*NBAS);
    }
  }
}

extern "C" void kernel_launch(void* const* d_in, const int* in_sizes, int n_in,
                              void* d_out, int out_size){
  const void* a = d_in[0];
  const void* c = d_in[1];
  const float2* pe;
  const float4* prm;
  if (in_sizes[0] > in_sizes[1]) { pe = (const float2*)a; prm = (const float4*)c; }
  else                           { pe = (const float2*)c; prm = (const float4*)a; }
  gr4j_ws2<<<NBAS / 64, 64>>>(pe, prm, (float*)d_out);
}

// round 5
// speedup vs baseline: 1.3356x; 1.3356x over previous
#include <cuda_runtime.h>
#include <cstdint>

#define NBAS  2048
#define TT    4015
#define CH    32
// chunks 0..124 full (t = 0..3999), chunk 125 = 15-step tail (t = 4000..4014)

__device__ __forceinline__ float sqrt_ap(float x){ float y; asm("sqrt.approx.f32 %0, %1;" : "=f"(y) : "f"(x)); return y; }
__device__ __forceinline__ float rsqrt_ap(float x){ float y; asm("rsqrt.approx.f32 %0, %1;" : "=f"(y) : "f"(x)); return y; }

__device__ __forceinline__ void bar_sync_id(int id){ asm volatile("bar.sync %0, 64;" :: "r"(id)); }
__device__ __forceinline__ void bar_arrive_id(int id){ asm volatile("bar.arrive %0, 64;" :: "r"(id)); }

__device__ __forceinline__ void cpa8(uint32_t saddr, const void* g){
  asm volatile("cp.async.ca.shared.global [%0], [%1], 8;" :: "r"(saddr), "l"(g));
}
__device__ __forceinline__ void cpa_commit(){ asm volatile("cp.async.commit_group;"); }
template<int N>
__device__ __forceinline__ void cpa_wait(){ asm volatile("cp.async.wait_group %0;" :: "n"(N)); }

// ---------------- production (s store) ----------------
// tanh(x) ~ x for x <= 0.01; 1/(1+d) ~ 1-d+d^2, d <= 0.01;
// (1+y)^(-1/4), y <= 0.039 -> 4-term Taylor. s2 clip provably inactive.
struct PSt { float s, inv_x1, c49; };

__device__ __forceinline__ float prod_step(PSt& st, float2 pe){
  float diff = pe.x - pe.y;
  float pn = fmaxf(diff, 0.f);
  float en = fmaxf(-diff, 0.f);
  float xp = pn * st.inv_x1;
  float xe = en * st.inv_x1;
  float u  = st.s * st.inv_x1;
  float dp = u * xp;
  float ip = fmaf(dp, dp - 1.f, 1.f);
  float ps = pn * fmaf(-u, u, 1.f) * ip;
  float de = (1.f - u) * xe;
  float ie = fmaf(de, de - 1.f, 1.f);
  float es = st.s * (2.f - u) * xe * ie;
  float s2 = (st.s - es) + ps;
  float m  = s2 * st.c49;
  float m2 = m * m;
  float y  = m2 * m2;
  float p  = fmaf(y, fmaf(y, -15.f/128.f, 5.f/32.f), -0.25f);
  float w  = fmaf(y, p, 1.f);
  float snew = s2 * w;
  float pr = (s2 - snew) + (pn - ps);
  st.s = snew;
  return pr;
}

// ---------------- conv + routing (r store) ----------------
struct RSt {
  float r, c35, ix3_4;
  float u10,u11,u12, u20,u21,u22,u23,u24,u25;
  float h1,h2,h3,h4,h5;
};

template<bool STORE>
__device__ __forceinline__ void cons_step(RSt& st, float pr, float* op){
  float q9 = st.u10*pr + st.u11*st.h1 + st.u12*st.h2;
  float q1 = st.u20*pr + st.u21*st.h1 + st.u22*st.h2
           + st.u23*st.h3 + st.u24*st.h4 + st.u25*st.h5;
  st.h5 = st.h4; st.h4 = st.h3; st.h3 = st.h2; st.h2 = st.h1; st.h1 = pr;
  float r   = st.r;
  float gex = st.c35 * (r * r * r) * sqrt_ap(r);
  float rr  = fmaxf((r + q9) + gex, 0.f);
  float t2  = rr * rr;
  float a   = fmaf(t2 * t2, st.ix3_4, 1.f);
  float w   = rsqrt_ap(sqrt_ap(a));
  float rn  = rr * w;
  st.r = rn;
  if (STORE){
    *op = (rr - rn) + fmaxf(q1 + gex, 0.f);
  }
}

__shared__ float2 pebuf[2][CH][32];
__shared__ float  prbuf[2][CH][32];

__global__ void __launch_bounds__(64)
gr4j_cp(const float2* __restrict__ pe, const float4* __restrict__ prm,
        float* __restrict__ out){
  int lane = threadIdx.x & 31;
  int wid  = threadIdx.x >> 5;
  int b    = blockIdx.x * 32 + lane;
  float4 pm = prm[b];

  if (wid == 0){
    // ================= PRODUCER =================
    PSt st;
    float x1 = fmaf(pm.x, 1100.f, 100.f);
    st.inv_x1 = 1.f / x1;
    st.c49 = (4.f/9.f) * st.inv_x1;
    st.s = 0.5f * x1;

    const char* gb = (const char*)(pe + b);
    // issue chunk k's 32 loads into pebuf[k&1]
    auto issue_chunk = [&](int k){
      int buf = k & 1;
      uint32_t sbase = (uint32_t)__cvta_generic_to_shared(&pebuf[buf][0][lane]);
      int tb = k * CH;
      #pragma unroll 8
      for (int j = 0; j < CH; j++){
        int tt = tb + j; tt = tt < TT ? tt : TT - 1;
        cpa8(sbase + j * 32 * 8, gb + (size_t)tt * (NBAS * 8));
      }
      cpa_commit();
    };

    issue_chunk(0);
    issue_chunk(1);

    for (int k = 0; k < 125; k++){
      if (k >= 2) bar_sync_id(3 + (k & 1));
      cpa_wait<1>();                   // chunk k resident
      int buf = k & 1;
      #pragma unroll 8
      for (int j = 0; j < CH; j++){
        float2 v = pebuf[buf][j][lane];
        prbuf[buf][j][lane] = prod_step(st, v);
      }
      bar_arrive_id(1 + (k & 1));
      if (k + 2 <= 125) issue_chunk(k + 2);
    }
    // tail chunk k=125 (15 steps), buf 1
    bar_sync_id(3 + 1);
    cpa_wait<0>();
    #pragma unroll 8
    for (int j = 0; j < 15; j++){
      float2 v = pebuf[1][j][lane];
      prbuf[1][j][lane] = prod_step(st, v);
    }
    bar_arrive_id(1 + 1);
  } else {
    // ================= CONSUMER =================
    RSt st;
    float x2 = fmaf(pm.y,   8.f,  -5.f);
    float x3 = fmaf(pm.z, 280.f,  20.f);
    float x4 = fmaf(pm.w,  1.8f,  1.1f);
    float ix3 = 1.f / x3;
    float i2  = ix3 * ix3;
    st.c35   = x2 * (ix3 * ix3 * ix3) * sqrtf(ix3);
    st.ix3_4 = i2 * i2;
    st.r = 0.5f * x3;

    float ix4 = 1.f / x4;
    float sh1[4], sh2[7];
    #pragma unroll
    for (int t = 0; t < 4; t++){
      float a = fminf((float)t * ix4, 1.f);
      sh1[t] = a * a * sqrtf(a);
    }
    #pragma unroll
    for (int t = 0; t < 7; t++){
      float rr = (float)t * ix4; float v;
      if ((float)t <= x4){ v = 0.5f * rr * rr * sqrtf(rr); }
      else { float mm = fmaxf(2.f - rr, 0.f); v = 1.f - 0.5f * mm * mm * sqrtf(mm); }
      sh2[t] = v;
    }
    st.u10 = sh1[1]-sh1[0]; st.u11 = sh1[2]-sh1[1]; st.u12 = sh1[3]-sh1[2];
    st.u20 = sh2[1]-sh2[0]; st.u21 = sh2[2]-sh2[1]; st.u22 = sh2[3]-sh2[2];
    st.u23 = sh2[4]-sh2[3]; st.u24 = sh2[5]-sh2[4]; st.u25 = sh2[6]-sh2[5];
    st.h1=0.f; st.h2=0.f; st.h3=0.f; st.h4=0.f; st.h5=0.f;

    // chunks 0..10: t = 0..351, no stores
    for (int k = 0; k < 11; k++){
      bar_sync_id(1 + (k & 1));
      int buf = k & 1;
      #pragma unroll 8
      for (int j = 0; j < CH; j++) cons_step<false>(st, prbuf[buf][j][lane], nullptr);
      bar_arrive_id(3 + (k & 1));
    }

    // chunk 11 (buf 1): t = 352..383; reset history before t=365 (j=13); store from j=13
    float* op = out + b;
    {
      bar_sync_id(1 + 1);
      #pragma unroll 8
      for (int j = 0; j < 13; j++) cons_step<false>(st, prbuf[1][j][lane], nullptr);
      st.h1=0.f; st.h2=0.f; st.h3=0.f; st.h4=0.f; st.h5=0.f;
      #pragma unroll 8
      for (int j = 13; j < CH; j++){
        cons_step<true>(st, prbuf[1][j][lane], op);
        op += NBAS;
      }
      bar_arrive_id(3 + 1);
    }

    // chunks 12..124: all store
    for (int k = 12; k < 125; k++){
      bar_sync_id(1 + (k & 1));
      int buf = k & 1;
      #pragma unroll 8
      for (int j = 0; j < CH; j++){
        cons_step<true>(st, prbuf[buf][j][lane], op);
        op += NBAS;
      }
      bar_arrive_id(3 + (k & 1));
    }

    // tail chunk 125 (buf 1): 15 steps -> ti 3635..3649
    bar_sync_id(1 + 1);
    #pragma unroll 8
    for (int j = 0; j < 15; j++){
      cons_step<true>(st, prbuf[1][j][lane], op);
      op += NBAS;
    }
  }
}

extern "C" void kernel_launch(void* const* d_in, const int* in_sizes, int n_in,
                              void* d_out, int out_size){
  const void* a = d_in[0];
  const void* c = d_in[1];
  const float2* pe;
  const float4* prm;
  if (in_sizes[0] > in_sizes[1]) { pe = (const float2*)a; prm = (const float4*)c; }
  else                           { pe = (const float2*)c; prm = (const float4*)a; }
  gr4j_cp<<<NBAS / 32, 64>>>(pe, prm, (float*)d_out);
}